// round 2
// baseline (speedup 1.0000x reference)
#include <cuda_runtime.h>

// Problem constants (fixed by setup_inputs)
#define Bn   16
#define D    1024
#define H    16
#define HD   64
#define S    4096
#define SP   4097          // S + 1
#define SPAD 4112          // padded score row stride
#define CH   256           // rows per chunk in streaming passes
#define NCH  17            // ceil(4097/256)
#define ET   32            // e-tile for score GEMM

// Scratch (device globals; no allocation allowed)
__device__ float g_qw[Bn * H * D];                       // 1 MB   projected query
__device__ float g_scores[Bn * H * SPAD];                // 4.2 MB scores -> attn (in place)
__device__ float g_avpart[(size_t)Bn * NCH * H * D];     // 17.8MB partial attn@V per chunk

// ---------------------------------------------------------------------------
// Kernel 1: q projection + fold through wk:
//   q[b,h,d]  = (query[b,:]·wq_row(h*64+d) + bq)*hd^-0.5
//   qw[b,h,e] = sum_d q[b,h,d] * wk[h*64+d, e]
// grid (H, B), 128 threads
// ---------------------------------------------------------------------------
__global__ void k_qproj(const float* __restrict__ query,
                        const float* __restrict__ w_in,
                        const float* __restrict__ b_in) {
    __shared__ float qs[D];
    __shared__ float qh[HD];
    const int h = blockIdx.x, b = blockIdx.y, tid = threadIdx.x;

    for (int i = tid; i < D; i += 128) qs[i] = query[b * D + i];
    __syncthreads();

    if (tid < HD) {
        const float* wrow = w_in + (size_t)(h * HD + tid) * D;
        float acc = 0.f;
        #pragma unroll 8
        for (int e = 0; e < D; e++) acc = fmaf(qs[e], wrow[e], acc);
        qh[tid] = (acc + b_in[h * HD + tid]) * 0.125f;  // hd^-0.5 = 1/8
    }
    __syncthreads();

    for (int e = tid; e < D; e += 128) {
        float acc = 0.f;
        #pragma unroll
        for (int d = 0; d < HD; d++)
            acc = fmaf(qh[d], w_in[(size_t)(D + h * HD + d) * D + e], acc);
        g_qw[(b * H + h) * D + e] = acc;
    }
}

// ---------------------------------------------------------------------------
// Kernel 2: stream keys -> write comb_key AND compute scores[b,h,k]
// Per block: batch b, chunk of 256 key rows. Register tile 4h x 8k per thread.
// grid (NCH, B), 128 threads (4 warps: warp = head-quad, lane = k-slot)
// ---------------------------------------------------------------------------
__global__ void __launch_bounds__(128) k_keys(const float* __restrict__ past_key,
                                              const float* __restrict__ key,
                                              float* __restrict__ comb_key) {
    __shared__ float ks[CH][ET + 1];   // stride 33: conflict-free scalar reads
    __shared__ float qws[H][ET + 1];

    const int chunk = blockIdx.x, b = blockIdx.y, tid = threadIdx.x;
    const int k0 = chunk * CH;
    const int rows = min(CH, SP - k0);
    const int hq = tid >> 5;           // warp id -> heads 4hq..4hq+3
    const int lane = tid & 31;         // k = lane + 32j

    float acc[4][8];
    #pragma unroll
    for (int a = 0; a < 4; a++)
        #pragma unroll
        for (int j = 0; j < 8; j++) acc[a][j] = 0.f;

    for (int et = 0; et < D; et += ET) {
        // qw tile: 16h x 32e
        for (int i = tid; i < H * ET; i += 128) {
            int h = i >> 5, e = i & 31;
            qws[h][e] = g_qw[((b * H + h) << 10) + et + e];
        }
        // key tile load (float4) + comb_key store
        for (int i = tid; i < CH * (ET / 4); i += 128) {
            int r = i >> 3, c = (i & 7) * 4;
            int kp = k0 + r;
            float4 v = make_float4(0.f, 0.f, 0.f, 0.f);
            if (r < rows) {
                const float* src = (kp < S)
                    ? past_key + ((size_t)(b * S + kp)) * D + et + c
                    : key + (size_t)b * D + et + c;
                v = *(const float4*)src;
                *(float4*)(comb_key + ((size_t)b * SP + kp) * D + et + c) = v;
            }
            ks[r][c] = v.x; ks[r][c + 1] = v.y; ks[r][c + 2] = v.z; ks[r][c + 3] = v.w;
        }
        __syncthreads();

        #pragma unroll 4
        for (int e = 0; e < ET; e++) {
            float kv[8];
            #pragma unroll
            for (int j = 0; j < 8; j++) kv[j] = ks[lane + 32 * j][e];
            #pragma unroll
            for (int hh = 0; hh < 4; hh++) {
                float qv = qws[4 * hq + hh][e];
                #pragma unroll
                for (int j = 0; j < 8; j++) acc[hh][j] = fmaf(qv, kv[j], acc[hh][j]);
            }
        }
        __syncthreads();
    }

    #pragma unroll
    for (int hh = 0; hh < 4; hh++)
        #pragma unroll
        for (int j = 0; j < 8; j++) {
            int k = lane + 32 * j;
            if (k0 + k < SP)
                g_scores[(size_t)(b * H + 4 * hq + hh) * SPAD + k0 + k] = acc[hh][j];
        }
}

// ---------------------------------------------------------------------------
// Kernel 3: softmax over 4097 scores per (b,h); in place. grid 256, 256 thr.
// ---------------------------------------------------------------------------
__global__ void k_softmax() {
    __shared__ float red[32];
    __shared__ float bc;
    const int tid = threadIdx.x, lane = tid & 31, wid = tid >> 5;
    float* row = g_scores + (size_t)blockIdx.x * SPAD;

    float m = -1e30f;
    for (int i = tid; i < SP; i += 256) m = fmaxf(m, row[i]);
    #pragma unroll
    for (int o = 16; o; o >>= 1) m = fmaxf(m, __shfl_xor_sync(0xffffffffu, m, o));
    if (lane == 0) red[wid] = m;
    __syncthreads();
    if (tid == 0) {
        float v = red[0];
        for (int i = 1; i < 8; i++) v = fmaxf(v, red[i]);
        bc = v;
    }
    __syncthreads();
    const float M = bc;

    float s = 0.f;
    for (int i = tid; i < SP; i += 256) {
        float e = __expf(row[i] - M);
        row[i] = e;
        s += e;
    }
    #pragma unroll
    for (int o = 16; o; o >>= 1) s += __shfl_xor_sync(0xffffffffu, s, o);
    if (lane == 0) red[wid] = s;
    __syncthreads();
    if (tid == 0) {
        float v = 0.f;
        for (int i = 0; i < 8; i++) v += red[i];
        bc = 1.f / v;
    }
    __syncthreads();
    const float inv = bc;
    for (int i = tid; i < SP; i += 256) row[i] *= inv;
}

// ---------------------------------------------------------------------------
// Kernel 4: stream values -> write comb_value AND accumulate
//   avpart[b,chunk,h,e] = sum_{k in chunk} attn[b,h,k] * comb_value[b,k,e]
// grid (NCH, B), 256 threads. Thread owns acc[4h][16e] in registers.
// ---------------------------------------------------------------------------
__global__ void __launch_bounds__(256) k_values(const float* __restrict__ past_value,
                                                const float* __restrict__ value,
                                                float* __restrict__ comb_value) {
    __shared__ float vs[8][D + 8];     // 8 staged rows, stride 1032 (16B aligned)
    __shared__ float as[8][16];        // attn weights for staged rows

    const int chunk = blockIdx.x, b = blockIdx.y, tid = threadIdx.x;
    const int k0 = chunk * CH;
    const int rows = min(CH, SP - k0);
    const int hq = tid >> 6;           // heads 4hq..4hq+3
    const int eq = tid & 63;           // e = eq + 64j

    float acc[4][16];
    #pragma unroll
    for (int a = 0; a < 4; a++)
        #pragma unroll
        for (int j = 0; j < 16; j++) acc[a][j] = 0.f;

    for (int rg = 0; rg < CH; rg += 8) {
        // stage 8 value rows (float4) + comb_value store
        for (int i = tid; i < 8 * (D / 4); i += 256) {
            int r = i >> 8, c = (i & 255) * 4;
            int kp = k0 + rg + r;
            float4 v = make_float4(0.f, 0.f, 0.f, 0.f);
            if (rg + r < rows) {
                const float* src = (kp < S)
                    ? past_value + ((size_t)(b * S + kp)) * D + c
                    : value + (size_t)b * D + c;
                v = *(const float4*)src;
                *(float4*)(comb_value + ((size_t)b * SP + kp) * D + c) = v;
            }
            *(float4*)&vs[r][c] = v;
        }
        // stage attn weights: as[r][h]
        if (tid < 128) {
            int h = tid >> 3, r = tid & 7;
            int kp = k0 + rg + r;
            as[r][h] = (kp < SP) ? g_scores[(size_t)(b * H + h) * SPAD + kp] : 0.f;
        }
        __syncthreads();

        #pragma unroll
        for (int r = 0; r < 8; r++) {
            float w[4];
            #pragma unroll
            for (int hh = 0; hh < 4; hh++) w[hh] = as[r][4 * hq + hh];
            #pragma unroll
            for (int j = 0; j < 16; j++) {
                float vv = vs[r][eq + 64 * j];
                #pragma unroll
                for (int hh = 0; hh < 4; hh++) acc[hh][j] = fmaf(w[hh], vv, acc[hh][j]);
            }
        }
        __syncthreads();
    }

    #pragma unroll
    for (int hh = 0; hh < 4; hh++)
        #pragma unroll
        for (int j = 0; j < 16; j++)
            g_avpart[(((size_t)b * NCH + chunk) * H + (4 * hq + hh)) * D + eq + 64 * j]
                = acc[hh][j];
}

// ---------------------------------------------------------------------------
// Kernel 5: combine chunk partials, ctx = av@wv.T + bv, out = ctx@w_out.T + b_out
// grid B, 256 threads.
// ---------------------------------------------------------------------------
__global__ void k_epilogue(const float* __restrict__ w_in,
                           const float* __restrict__ b_in,
                           const float* __restrict__ w_out,
                           const float* __restrict__ b_out,
                           float* __restrict__ out) {
    __shared__ float avs[D];
    __shared__ float ctx_s[D];
    const int b = blockIdx.x, tid = threadIdx.x;

    for (int h = 0; h < H; h++) {
        for (int e = tid; e < D; e += 256) {
            float s = 0.f;
            #pragma unroll
            for (int c = 0; c < NCH; c++)
                s += g_avpart[(((size_t)b * NCH + c) * H + h) * D + e];
            avs[e] = s;
        }
        __syncthreads();

        int d = tid >> 2, sub = tid & 3;    // 64 d, 4 partials each
        const float* wrow = w_in + (size_t)(2 * D + h * HD + d) * D;
        float acc = 0.f;
        for (int e = sub; e < D; e += 4) acc = fmaf(avs[e], wrow[e], acc);
        acc += __shfl_down_sync(0xffffffffu, acc, 2, 4);
        acc += __shfl_down_sync(0xffffffffu, acc, 1, 4);
        if (sub == 0) ctx_s[h * HD + d] = acc + b_in[2 * D + h * HD + d];
        __syncthreads();
    }

    for (int o = tid; o < D; o += 256) {
        const float* wrow = w_out + (size_t)o * D;
        float acc = b_out[o];
        #pragma unroll 8
        for (int dt = 0; dt < D; dt++) acc = fmaf(ctx_s[dt], wrow[dt], acc);
        out[(size_t)b * D + o] = acc;
    }
}

// ---------------------------------------------------------------------------
extern "C" void kernel_launch(void* const* d_in, const int* in_sizes, int n_in,
                              void* d_out, int out_size) {
    (void)in_sizes; (void)n_in; (void)out_size;
    const float* query      = (const float*)d_in[0];
    const float* key        = (const float*)d_in[1];
    const float* value      = (const float*)d_in[2];
    const float* past_key   = (const float*)d_in[3];
    const float* past_value = (const float*)d_in[4];
    const float* w_in       = (const float*)d_in[5];
    const float* b_in       = (const float*)d_in[6];
    const float* w_out      = (const float*)d_in[7];
    const float* b_out      = (const float*)d_in[8];

    float* out        = (float*)d_out;                      // [16,1,1024]
    float* comb_key   = out + (size_t)Bn * D;               // [16,4097,1024]
    float* comb_value = comb_key + (size_t)Bn * SP * D;     // [16,4097,1024]

    k_qproj<<<dim3(H, Bn), 128>>>(query, w_in, b_in);
    k_keys<<<dim3(NCH, Bn), 128>>>(past_key, key, comb_key);
    k_softmax<<<Bn * H, 256>>>();
    k_values<<<dim3(NCH, Bn), 256>>>(past_value, value, comb_value);
    k_epilogue<<<Bn, 256>>>(w_in, b_in, w_out, b_out, out);
}

// round 3
// speedup vs baseline: 3.5384x; 3.5384x over previous
#include <cuda_runtime.h>

// Problem constants (fixed by setup_inputs)
#define Bn   16
#define D    1024
#define H    16
#define HD   64
#define S    4096
#define SP   4097          // S + 1
#define SPAD 4112          // padded score row stride

// key pass tiling
#define KCH  128           // key rows per block
#define KNC  33            // ceil(4097/128)
#define KET  16            // e columns per tile
#define KSTR 20            // smem row stride (floats): conflict-free LDS.128

// value pass tiling
#define VCH  128           // value rows per block
#define VNC  33
#define VROWS 4            // rows per pipeline stage
#define VSTR 1032          // smem row stride (floats)

// Scratch (device globals; no allocation allowed)
__device__ float g_qw[Bn * H * D];                        // q @ wk^T folded query
__device__ float g_scores[Bn * H * SPAD];                 // scores -> attn in place
__device__ float g_avpart[(size_t)Bn * VNC * H * D];      // chunk partial attn@V
__device__ float g_ctx[Bn * D];                           // per-batch context

// ---------------------------------------------------------------------------
// cp.async helpers
// ---------------------------------------------------------------------------
__device__ __forceinline__ void cp16(void* s, const void* g) {
    unsigned a = (unsigned)__cvta_generic_to_shared(s);
    asm volatile("cp.async.cg.shared.global [%0], [%1], 16;" :: "r"(a), "l"(g));
}
__device__ __forceinline__ void cp_commit() { asm volatile("cp.async.commit_group;"); }
__device__ __forceinline__ void cp_wait1()  { asm volatile("cp.async.wait_group 1;"); }
__device__ __forceinline__ void cp_wait0()  { asm volatile("cp.async.wait_group 0;"); }

// ---------------------------------------------------------------------------
// Kernel 1: q projection folded through wk:
//   qh[d]  = (query[b,:]·wq_row(h*64+d) + bq)*0.125
//   qw[b,h,e] = sum_d qh[d] * wk[h*64+d, e]
// grid (H, B), 256 threads
// ---------------------------------------------------------------------------
__global__ void __launch_bounds__(256) k_qproj(const float* __restrict__ query,
                                               const float* __restrict__ w_in,
                                               const float* __restrict__ b_in) {
    __shared__ float qs[D];
    __shared__ float qh[HD];
    const int h = blockIdx.x, b = blockIdx.y, tid = threadIdx.x;

    for (int i = tid; i < D; i += 256) qs[i] = query[b * D + i];
    __syncthreads();

    {   // 64 outputs x 4 threads each
        int d = tid >> 2, sub = tid & 3;
        const float* wrow = w_in + (size_t)(h * HD + d) * D;
        float a = 0.f;
        #pragma unroll 8
        for (int e = sub; e < D; e += 4) a = fmaf(qs[e], wrow[e], a);
        a += __shfl_down_sync(0xffffffffu, a, 2, 4);
        a += __shfl_down_sync(0xffffffffu, a, 1, 4);
        if (sub == 0) qh[d] = (a + b_in[h * HD + d]) * 0.125f;
    }
    __syncthreads();

    for (int e = tid; e < D; e += 256) {
        float a = 0.f;
        #pragma unroll
        for (int d = 0; d < HD; d++)
            a = fmaf(qh[d], w_in[(size_t)(D + h * HD + d) * D + e], a);
        g_qw[(b * H + h) * D + e] = a;
    }
}

// ---------------------------------------------------------------------------
// Kernel 2: key pass — cp.async double-buffered.
//   copies past_key/key -> comb_key AND computes scores[b,h,k] = key_k · qw[b,h]
// grid (KNC, B), 128 threads. Warp = 4 heads; lane owns k = lane + 32*jj.
// ---------------------------------------------------------------------------
__global__ void __launch_bounds__(128) k_keys(const float* __restrict__ past_key,
                                              const float* __restrict__ key,
                                              float* __restrict__ comb_key) {
    __shared__ float ks[2][KCH][KSTR];
    __shared__ float qws[H][KSTR];

    const int chunk = blockIdx.x, b = blockIdx.y, tid = threadIdx.x;
    const int k0 = chunk * KCH;
    const int hq = tid >> 5, lane = tid & 31;

    float acc[4][4];
    #pragma unroll
    for (int a = 0; a < 4; a++)
        #pragma unroll
        for (int j = 0; j < 4; j++) acc[a][j] = 0.f;

    // prologue: tile 0
    #pragma unroll
    for (int m = 0; m < 4; m++) {
        int i = tid + 128 * m;
        int r = i >> 2, c = (i & 3) * 4;
        int kp = k0 + r;
        const float* src = (kp < S) ? past_key + ((size_t)b * S + kp) * D
                                    : key + (size_t)b * D;
        cp16(&ks[0][r][c], src + c);
    }
    cp_commit();

    for (int t = 0; t < D / KET; t++) {
        const int et = t * KET;
        __syncthreads();                        // prev compute done: qws + other buf free

        // qw tile for this block of e columns
        for (int i = tid; i < H * KET; i += 128) {
            int h = i >> 4, e = i & 15;
            qws[h][e] = g_qw[((b * H + h) << 10) + et + e];
        }
        if (t + 1 < D / KET) {
            const int et2 = et + KET, bufn = (t + 1) & 1;
            #pragma unroll
            for (int m = 0; m < 4; m++) {
                int i = tid + 128 * m;
                int r = i >> 2, c = (i & 3) * 4;
                int kp = k0 + r;
                const float* src = (kp < S) ? past_key + ((size_t)b * S + kp) * D
                                            : key + (size_t)b * D;
                cp16(&ks[bufn][r][c], src + et2 + c);
            }
            cp_commit();
            cp_wait1();
        } else {
            cp_wait0();
        }
        __syncthreads();                        // tile t data + qws visible

        const int buf = t & 1;
        // comb_key store from smem
        #pragma unroll
        for (int m = 0; m < 4; m++) {
            int i = tid + 128 * m;
            int r = i >> 2, c = (i & 3) * 4;
            int kp = k0 + r;
            if (kp < SP)
                *(float4*)(comb_key + ((size_t)b * SP + kp) * D + et + c)
                    = *(float4*)&ks[buf][r][c];
        }
        // score tile: 4h x 4k register block, float4 over e
        #pragma unroll
        for (int e4 = 0; e4 < KET / 4; e4++) {
            float4 kv[4];
            #pragma unroll
            for (int jj = 0; jj < 4; jj++)
                kv[jj] = *(float4*)&ks[buf][lane + 32 * jj][e4 * 4];
            #pragma unroll
            for (int hh = 0; hh < 4; hh++) {
                float4 q4 = *(float4*)&qws[4 * hq + hh][e4 * 4];
                #pragma unroll
                for (int jj = 0; jj < 4; jj++) {
                    acc[hh][jj] = fmaf(q4.x, kv[jj].x, acc[hh][jj]);
                    acc[hh][jj] = fmaf(q4.y, kv[jj].y, acc[hh][jj]);
                    acc[hh][jj] = fmaf(q4.z, kv[jj].z, acc[hh][jj]);
                    acc[hh][jj] = fmaf(q4.w, kv[jj].w, acc[hh][jj]);
                }
            }
        }
    }

    #pragma unroll
    for (int hh = 0; hh < 4; hh++)
        #pragma unroll
        for (int jj = 0; jj < 4; jj++) {
            int k = k0 + lane + 32 * jj;
            if (k < SP)
                g_scores[(size_t)(b * H + 4 * hq + hh) * SPAD + k] = acc[hh][jj];
        }
}

// ---------------------------------------------------------------------------
// Kernel 3: softmax over 4097 scores per (b,h); in place. grid 256, 256 thr.
// ---------------------------------------------------------------------------
__global__ void k_softmax() {
    __shared__ float red[32];
    __shared__ float bc;
    const int tid = threadIdx.x, lane = tid & 31, wid = tid >> 5;
    float* row = g_scores + (size_t)blockIdx.x * SPAD;

    float m = -1e30f;
    for (int i = tid; i < SP; i += 256) m = fmaxf(m, row[i]);
    #pragma unroll
    for (int o = 16; o; o >>= 1) m = fmaxf(m, __shfl_xor_sync(0xffffffffu, m, o));
    if (lane == 0) red[wid] = m;
    __syncthreads();
    if (tid == 0) {
        float v = red[0];
        for (int i = 1; i < 8; i++) v = fmaxf(v, red[i]);
        bc = v;
    }
    __syncthreads();
    const float M = bc;

    float s = 0.f;
    for (int i = tid; i < SP; i += 256) {
        float e = __expf(row[i] - M);
        row[i] = e;
        s += e;
    }
    #pragma unroll
    for (int o = 16; o; o >>= 1) s += __shfl_xor_sync(0xffffffffu, s, o);
    if (lane == 0) red[wid] = s;
    __syncthreads();
    if (tid == 0) {
        float v = 0.f;
        for (int i = 0; i < 8; i++) v += red[i];
        bc = 1.f / v;
    }
    __syncthreads();
    const float inv = bc;
    for (int i = tid; i < SP; i += 256) row[i] *= inv;
}

// ---------------------------------------------------------------------------
// Kernel 4: value pass — cp.async double-buffered stages of 4 rows.
//   copies past_value/value -> comb_value AND accumulates
//   avpart[b,chunk,h,e] = sum_{k in chunk} attn[b,h,k] * v[b,k,e]
// grid (VNC, B), 256 threads. Thread owns acc[4h][16e].
// ---------------------------------------------------------------------------
__global__ void __launch_bounds__(256) k_values(const float* __restrict__ past_value,
                                                const float* __restrict__ value,
                                                float* __restrict__ comb_value) {
    __shared__ float vs[2][VROWS][VSTR];
    __shared__ float as[VROWS][16];

    const int chunk = blockIdx.x, b = blockIdx.y, tid = threadIdx.x;
    const int k0 = chunk * VCH;
    const int hq = tid >> 6, eq = tid & 63;

    float acc[4][16];
    #pragma unroll
    for (int a = 0; a < 4; a++)
        #pragma unroll
        for (int j = 0; j < 16; j++) acc[a][j] = 0.f;

    // prologue: stage 0 (rows k0..k0+3)
    #pragma unroll
    for (int m = 0; m < 4; m++) {
        int i = tid + 256 * m;
        int r = i >> 8, c = (i & 255) * 4;
        int kp = k0 + r;
        const float* src = (kp < S) ? past_value + ((size_t)b * S + kp) * D
                                    : value + (size_t)b * D;
        cp16(&vs[0][r][c], src + c);
    }
    cp_commit();

    for (int st = 0; st < VCH / VROWS; st++) {
        __syncthreads();                        // prev compute done

        // attn weights for stage st (single-buffered: guarded by the two syncs)
        if (tid < 64) {
            int r = tid >> 4, h = tid & 15;
            int kp = k0 + st * VROWS + r;
            as[r][h] = (kp < SP) ? g_scores[(size_t)(b * H + h) * SPAD + kp] : 0.f;
        }
        if (st + 1 < VCH / VROWS) {
            const int base = k0 + (st + 1) * VROWS, bufn = (st + 1) & 1;
            #pragma unroll
            for (int m = 0; m < 4; m++) {
                int i = tid + 256 * m;
                int r = i >> 8, c = (i & 255) * 4;
                int kp = base + r;
                const float* src = (kp < S) ? past_value + ((size_t)b * S + kp) * D
                                            : value + (size_t)b * D;
                cp16(&vs[bufn][r][c], src + c);
            }
            cp_commit();
            cp_wait1();
        } else {
            cp_wait0();
        }
        __syncthreads();                        // stage st data + attn visible

        const int buf = st & 1;
        // comb_value store from smem
        #pragma unroll
        for (int m = 0; m < 4; m++) {
            int i = tid + 256 * m;
            int r = i >> 8, c = (i & 255) * 4;
            int kp = k0 + st * VROWS + r;
            if (kp < SP)
                *(float4*)(comb_value + ((size_t)b * SP + kp) * D + c)
                    = *(float4*)&vs[buf][r][c];
        }
        // accumulate
        #pragma unroll
        for (int r = 0; r < VROWS; r++) {
            float w[4];
            #pragma unroll
            for (int hh = 0; hh < 4; hh++) w[hh] = as[r][4 * hq + hh];
            #pragma unroll
            for (int j = 0; j < 16; j++) {
                float vv = vs[buf][r][eq + 64 * j];
                #pragma unroll
                for (int hh = 0; hh < 4; hh++)
                    acc[hh][j] = fmaf(w[hh], vv, acc[hh][j]);
            }
        }
    }

    #pragma unroll
    for (int hh = 0; hh < 4; hh++)
        #pragma unroll
        for (int j = 0; j < 16; j++)
            g_avpart[(((size_t)b * VNC + chunk) * H + (4 * hq + hh)) * D + eq + 64 * j]
                = acc[hh][j];
}

// ---------------------------------------------------------------------------
// Kernel 5: fold chunk partials + ctx = av @ wv^T + bv.  grid (H, B), 256 thr.
// ---------------------------------------------------------------------------
__global__ void __launch_bounds__(256) k_fold(const float* __restrict__ w_in,
                                              const float* __restrict__ b_in) {
    __shared__ float avs[D];
    const int h = blockIdx.x, b = blockIdx.y, tid = threadIdx.x;

    for (int e = tid; e < D; e += 256) {
        float s = 0.f;
        #pragma unroll
        for (int c = 0; c < VNC; c++)
            s += g_avpart[(((size_t)b * VNC + c) * H + h) * D + e];
        avs[e] = s;
    }
    __syncthreads();

    int d = tid >> 2, sub = tid & 3;
    const float* wrow = w_in + (size_t)(2 * D + h * HD + d) * D;
    float a = 0.f;
    #pragma unroll 8
    for (int e = sub; e < D; e += 4) a = fmaf(avs[e], wrow[e], a);
    a += __shfl_down_sync(0xffffffffu, a, 2, 4);
    a += __shfl_down_sync(0xffffffffu, a, 1, 4);
    if (sub == 0) g_ctx[b * D + h * HD + d] = a + b_in[2 * D + h * HD + d];
}

// ---------------------------------------------------------------------------
// Kernel 6: out = ctx @ w_out^T + b_out.  grid (16, B), 256 thr (64 outs/block).
// ---------------------------------------------------------------------------
__global__ void __launch_bounds__(256) k_out(const float* __restrict__ w_out,
                                             const float* __restrict__ b_out,
                                             float* __restrict__ out) {
    __shared__ float cs[D];
    const int og = blockIdx.x, b = blockIdx.y, tid = threadIdx.x;

    for (int i = tid; i < D; i += 256) cs[i] = g_ctx[b * D + i];
    __syncthreads();

    int o = og * 64 + (tid >> 2), sub = tid & 3;
    const float* wrow = w_out + (size_t)o * D;
    float a = 0.f;
    #pragma unroll 8
    for (int dt = sub; dt < D; dt += 4) a = fmaf(cs[dt], wrow[dt], a);
    a += __shfl_down_sync(0xffffffffu, a, 2, 4);
    a += __shfl_down_sync(0xffffffffu, a, 1, 4);
    if (sub == 0) out[(size_t)b * D + o] = a + b_out[o];
}

// ---------------------------------------------------------------------------
extern "C" void kernel_launch(void* const* d_in, const int* in_sizes, int n_in,
                              void* d_out, int out_size) {
    (void)in_sizes; (void)n_in; (void)out_size;
    const float* query      = (const float*)d_in[0];
    const float* key        = (const float*)d_in[1];
    const float* value      = (const float*)d_in[2];
    const float* past_key   = (const float*)d_in[3];
    const float* past_value = (const float*)d_in[4];
    const float* w_in       = (const float*)d_in[5];
    const float* b_in       = (const float*)d_in[6];
    const float* w_out      = (const float*)d_in[7];
    const float* b_out      = (const float*)d_in[8];

    float* out        = (float*)d_out;                      // [16,1,1024]
    float* comb_key   = out + (size_t)Bn * D;               // [16,4097,1024]
    float* comb_value = comb_key + (size_t)Bn * SP * D;     // [16,4097,1024]

    k_qproj  <<<dim3(H, Bn),   256>>>(query, w_in, b_in);
    k_keys   <<<dim3(KNC, Bn), 128>>>(past_key, key, comb_key);
    k_softmax<<<Bn * H,        256>>>();
    k_values <<<dim3(VNC, Bn), 256>>>(past_value, value, comb_value);
    k_fold   <<<dim3(H, Bn),   256>>>(w_in, b_in);
    k_out    <<<dim3(16, Bn),  256>>>(w_out, b_out, out);
}